// round 15
// baseline (speedup 1.0000x reference)
#include <cuda_runtime.h>
#include <cuda_fp16.h>
#include <cstdint>

#define DIMC 128
#define HID  512
#define TILE_M 64
#define THREADS 128
#define EPSV 1e-5f

#define ROWB 272
#define ATILE_BYTES (64 * ROWB)        // 17408

// ---- smem: xn + 4 H chunk buffers = 87040 -> 2 CTAs/SM
#define SM_XN 0
#define SM_H  (SM_XN + ATILE_BYTES)
#define SM_TOTAL (SM_H + 4 * ATILE_BYTES)

// ---- fragment-ordered fp16 weight images: [chunk][nw][iter=ks*4+ng][lane]
__device__ __align__(16) uint4 g_w1f[4][2][32][32];
__device__ __align__(16) uint4 g_w2f[4][2][32][32];

// ---------------- PTX helpers ----------------
__device__ __forceinline__ uint32_t smem_u32(const void* p) {
    uint32_t a;
    asm("{ .reg .u64 t; cvta.to.shared.u64 t, %1; cvt.u32.u64 %0, t; }" : "=r"(a) : "l"(p));
    return a;
}

__device__ __forceinline__ void ldsm4(uint32_t r[4], uint32_t addr) {
    asm volatile("ldmatrix.sync.aligned.m8n8.x4.shared.b16 {%0,%1,%2,%3}, [%4];"
                 : "=r"(r[0]), "=r"(r[1]), "=r"(r[2]), "=r"(r[3]) : "r"(addr));
}

__device__ __forceinline__ void mma16816(float c[4], const uint32_t a[4],
                                         uint32_t b0, uint32_t b1) {
    asm volatile(
        "mma.sync.aligned.m16n8k16.row.col.f32.f16.f16.f32 "
        "{%0,%1,%2,%3}, {%4,%5,%6,%7}, {%8,%9}, {%0,%1,%2,%3};"
        : "+f"(c[0]), "+f"(c[1]), "+f"(c[2]), "+f"(c[3])
        : "r"(a[0]), "r"(a[1]), "r"(a[2]), "r"(a[3]), "r"(b0), "r"(b1));
}

__device__ __forceinline__ uint32_t pack_f16x2(float lo, float hi) {
    uint32_t r;
    asm("cvt.rn.f16x2.f32 %0, %1, %2;" : "=r"(r) : "f"(hi), "f"(lo));
    return r;
}

__device__ __forceinline__ uint32_t relu_bias_h2(uint32_t v, uint32_t bias) {
    const __half2 z = __float2half2_rn(0.0f);
    __half2 h = __hadd2(*(__half2*)&v, *(__half2*)&bias);
    h = __hmax2(h, z);
    return *(uint32_t*)&h;
}

__device__ __forceinline__ uint32_t pack2h(__half a, __half b) {
    __half2 t; t.x = a; t.y = b;
    return *(uint32_t*)&t;
}

// ---------------- prep: weights -> fragment-ordered fp16 images ----------
__global__ void prep_weights(const float* __restrict__ w1, const float* __restrict__ w2) {
    const int idx  = blockIdx.x * blockDim.x + threadIdx.x;   // 0..16383
    const int lane = idx & 31;
    const int iter = (idx >> 5) & 31;
    const int nw   = (idx >> 10) & 1;
    const int c    = (idx >> 11) & 3;
    const int mat  = idx >> 13;

    const int ks = iter >> 2, ng = iter & 3;
    const int n0 = nw * 64 + ng * 16 + (lane >> 2);
    const int k0 = ks * 16 + (lane & 3) * 2;

    uint4 v;
    if (mat == 0) {
        #define E1(n, k) __float2half_rn(w1[(size_t)(c * 128 + (n)) * DIMC + (k)])
        v.x = pack2h(E1(n0,     k0),     E1(n0,     k0 + 1));
        v.y = pack2h(E1(n0,     k0 + 8), E1(n0,     k0 + 9));
        v.z = pack2h(E1(n0 + 8, k0),     E1(n0 + 8, k0 + 1));
        v.w = pack2h(E1(n0 + 8, k0 + 8), E1(n0 + 8, k0 + 9));
        #undef E1
        g_w1f[c][nw][iter][lane] = v;
    } else {
        #define E2(n, k) __float2half_rn(w2[(size_t)(n) * HID + c * 128 + (k)])
        v.x = pack2h(E2(n0,     k0),     E2(n0,     k0 + 1));
        v.y = pack2h(E2(n0,     k0 + 8), E2(n0,     k0 + 9));
        v.z = pack2h(E2(n0 + 8, k0),     E2(n0 + 8, k0 + 1));
        v.w = pack2h(E2(n0 + 8, k0 + 8), E2(n0 + 8, k0 + 9));
        #undef E2
        g_w2f[c][nw][iter][lane] = v;
    }
}

// MMA sub-step with preloaded A fragments: 4 B-LDG + 16 MMA
__device__ __forceinline__ void mma_sub(const uint32_t a0[4], const uint32_t a1[4],
                                        const uint4* __restrict__ bp,
                                        int ks, float acc[2][8][4]) {
    #pragma unroll
    for (int ng = 0; ng < 4; ++ng) {
        const uint4 rb = __ldg(bp + (ks * 4 + ng) * 32);
        mma16816(acc[0][2*ng],   a0, rb.x, rb.y);
        mma16816(acc[1][2*ng],   a1, rb.x, rb.y);
        mma16816(acc[0][2*ng+1], a0, rb.z, rb.w);
        mma16816(acc[1][2*ng+1], a1, rb.z, rb.w);
    }
}

// one ks step with A from smem (G2 path)
__device__ __forceinline__ void gemm_ks(uint32_t aAddr, const uint4* __restrict__ bp,
                                        int ks, float acc[2][8][4]) {
    uint32_t a0[4], a1[4];
    ldsm4(a0, aAddr + ks * 32);
    ldsm4(a1, aAddr + 16 * ROWB + ks * 32);
    mma_sub(a0, a1, bp, ks, acc);
}

#define ZERO_ACC(A) \
    { _Pragma("unroll") for (int i = 0; i < 2; ++i) \
      _Pragma("unroll") for (int j = 0; j < 8; ++j) \
      _Pragma("unroll") for (int k = 0; k < 4; ++k) (A)[i][j][k] = 0.0f; }

// ---------------- main fused kernel ----------------
__global__ void __launch_bounds__(THREADS, 2)
fused_ln_mlp_hmma(const float* __restrict__ x,
                  const float* __restrict__ b1,
                  const float* __restrict__ b2,
                  const float* __restrict__ wn,
                  const float* __restrict__ bn,
                  float* __restrict__ out)
{
    extern __shared__ __align__(16) unsigned char smem[];
    const uint32_t sb = smem_u32(smem);

    const int tid  = threadIdx.x;
    const int lane = tid & 31;
    const int warp = tid >> 5;
    const int mw   = warp & 1;
    const int nw   = warp >> 1;
    const long long m0 = (long long)blockIdx.x * TILE_M;

    // -------- Stage A: LayerNorm -> xn fp16 tile --------
    {
        const float4 wn4 = *(const float4*)(wn + lane * 4);
        const float4 bn4 = *(const float4*)(bn + lane * 4);
        #pragma unroll
        for (int t = 0; t < 16; ++t) {
            const int tok = warp * 16 + t;
            float4 v = *(const float4*)(x + (m0 + tok) * DIMC + lane * 4);
            float s = v.x + v.y + v.z + v.w;
            float q = v.x*v.x + v.y*v.y + v.z*v.z + v.w*v.w;
            #pragma unroll
            for (int o = 16; o > 0; o >>= 1) {
                s += __shfl_xor_sync(0xffffffffu, s, o);
                q += __shfl_xor_sync(0xffffffffu, q, o);
            }
            const float mu  = s * (1.0f / DIMC);
            const float var = q * (1.0f / DIMC) - mu * mu;
            const float r   = rsqrtf(var + EPSV);
            const uint32_t p0 = pack_f16x2((v.x - mu) * r * wn4.x + bn4.x,
                                           (v.y - mu) * r * wn4.y + bn4.y);
            const uint32_t p1 = pack_f16x2((v.z - mu) * r * wn4.z + bn4.z,
                                           (v.w - mu) * r * wn4.w + bn4.w);
            const uint32_t off = (uint32_t)tok * ROWB + lane * 8;
            *(uint2*)(smem + SM_XN + off) = make_uint2(p0, p1);
        }
    }
    __syncthreads();

    // per-thread addressing
    const uint32_t a_row = (uint32_t)(mw * 32 + (lane & 15)) * ROWB + ((lane >> 4) << 4);
    const uint32_t aXn   = sb + SM_XN + a_row;
    const uint32_t h_sts0 = (uint32_t)(mw * 32 + (lane >> 2)) * ROWB
                          + (uint32_t)(nw * 64 + (lane & 3) * 2) * 2;
    const int colb = nw * 64 + (lane & 3) * 2;

    // -------- Phase 1: G1 in chunk PAIRS sharing A-LDSM ------------------
    float accA[2][8][4], accB[2][8][4];
    uint32_t hp[16][2];

    // pack helper (macro to avoid array-copy): acc -> hp with +b1, relu
    #define PACK_CHUNK(ACC, C)                                                  \
    {                                                                           \
        const float* b1c = b1 + (C) * 128;                                      \
        _Pragma("unroll")                                                       \
        for (int mt = 0; mt < 2; ++mt)                                          \
            _Pragma("unroll")                                                   \
            for (int nt = 0; nt < 8; ++nt) {                                    \
                const uint32_t hb = pack_f16x2(__ldg(b1c + colb + nt * 8),      \
                                               __ldg(b1c + colb + nt * 8 + 1)); \
                hp[mt * 8 + nt][0] = relu_bias_h2(                              \
                    pack_f16x2((ACC)[mt][nt][0], (ACC)[mt][nt][1]), hb);        \
                hp[mt * 8 + nt][1] = relu_bias_h2(                              \
                    pack_f16x2((ACC)[mt][nt][2], (ACC)[mt][nt][3]), hb);        \
            }                                                                   \
    }

    #define STORE_HP_ALL(C)                                                     \
    {                                                                           \
        const uint32_t hbase = SM_H + (uint32_t)(C) * ATILE_BYTES + h_sts0;     \
        _Pragma("unroll")                                                       \
        for (int f = 0; f < 16; ++f) {                                          \
            const int mt = f >> 3, nt = f & 7;                                  \
            const uint32_t o0 = hbase + (uint32_t)mt * (16 * ROWB) + nt * 16;   \
            *(uint32_t*)(smem + o0)            = hp[f][0];                      \
            *(uint32_t*)(smem + o0 + 8 * ROWB) = hp[f][1];                      \
        }                                                                       \
    }

    // ---- pair (0,1): one A-load serves both chunks ----
    ZERO_ACC(accA); ZERO_ACC(accB);
    {
        const uint4* __restrict__ bp0 = &g_w1f[0][nw][0][lane];
        const uint4* __restrict__ bp1 = &g_w1f[1][nw][0][lane];
        #pragma unroll
        for (int ks = 0; ks < 8; ++ks) {
            uint32_t a0[4], a1[4];
            ldsm4(a0, aXn + ks * 32);
            ldsm4(a1, aXn + 16 * ROWB + ks * 32);
            mma_sub(a0, a1, bp0, ks, accA);
            mma_sub(a0, a1, bp1, ks, accB);
        }
    }

    // chunk 0: pack + store exposed
    PACK_CHUNK(accA, 0);
    STORE_HP_ALL(0);
    // chunk 1: pack now, stores hidden under pair (2,3)
    PACK_CHUNK(accB, 1);

    // ---- pair (2,3) with interleaved hp(1) stores ----
    ZERO_ACC(accA); ZERO_ACC(accB);
    {
        const uint32_t hbase1 = SM_H + (uint32_t)1 * ATILE_BYTES + h_sts0;
        const uint4* __restrict__ bp2 = &g_w1f[2][nw][0][lane];
        const uint4* __restrict__ bp3 = &g_w1f[3][nw][0][lane];
        #pragma unroll
        for (int ks = 0; ks < 8; ++ks) {
            uint32_t a0[4], a1[4];
            ldsm4(a0, aXn + ks * 32);
            ldsm4(a1, aXn + 16 * ROWB + ks * 32);
            mma_sub(a0, a1, bp2, ks, accA);
            mma_sub(a0, a1, bp3, ks, accB);
            #pragma unroll
            for (int f = 2 * ks; f < 2 * ks + 2; ++f) {
                const int mt = f >> 3, nt = f & 7;
                const uint32_t o0 = hbase1 + (uint32_t)mt * (16 * ROWB) + nt * 16;
                *(uint32_t*)(smem + o0)            = hp[f][0];
                *(uint32_t*)(smem + o0 + 8 * ROWB) = hp[f][1];
            }
        }
    }

    // chunks 2,3: pack + store exposed
    PACK_CHUNK(accA, 2);
    STORE_HP_ALL(2);
    PACK_CHUNK(accB, 3);
    STORE_HP_ALL(3);

    __syncthreads();   // all H chunks visible

    // -------- Phase 2: G2 chunks, acc2 accumulates (A differs per chunk) --
    float acc2[2][8][4];
    ZERO_ACC(acc2);

    #pragma unroll
    for (int c = 0; c < 4; ++c) {
        const uint32_t hA = sb + SM_H + (uint32_t)c * ATILE_BYTES + a_row;
        const uint4* __restrict__ bp = &g_w2f[c][nw][0][lane];
        #pragma unroll
        for (int ks = 0; ks < 8; ++ks) gemm_ks(hA, bp, ks, acc2);
    }

    // -------- final epilogue: acc2 + b2 -> out --------
    #pragma unroll
    for (int mt = 0; mt < 2; ++mt) {
        const long long row0 = m0 + mw * 32 + mt * 16 + (lane >> 2);
        #pragma unroll
        for (int nt = 0; nt < 8; ++nt) {
            const int col = nw * 64 + nt * 8 + (lane & 3) * 2;
            const float bb0 = __ldg(b2 + col), bb1 = __ldg(b2 + col + 1);
            float2 u, w;
            u.x = acc2[mt][nt][0] + bb0;  u.y = acc2[mt][nt][1] + bb1;
            w.x = acc2[mt][nt][2] + bb0;  w.y = acc2[mt][nt][3] + bb1;
            *(float2*)(out + row0 * DIMC + col)       = u;
            *(float2*)(out + (row0 + 8) * DIMC + col) = w;
        }
    }

    #undef PACK_CHUNK
    #undef STORE_HP_ALL
}

extern "C" void kernel_launch(void* const* d_in, const int* in_sizes, int n_in,
                              void* d_out, int out_size) {
    const float* x  = (const float*)d_in[0];
    const float* w1 = (const float*)d_in[1];
    const float* w2 = (const float*)d_in[2];
    const float* b1 = (const float*)d_in[3];
    const float* b2 = (const float*)d_in[4];
    const float* wn = (const float*)d_in[5];
    const float* bn = (const float*)d_in[6];
    float* out = (float*)d_out;

    prep_weights<<<64, 256>>>(w1, w2);

    const int T = in_sizes[0] / DIMC;        // 262144 tokens
    const int grid = T / TILE_M;             // 4096 CTAs

    cudaFuncSetAttribute(fused_ln_mlp_hmma,
                         cudaFuncAttributeMaxDynamicSharedMemorySize, SM_TOTAL);
    fused_ln_mlp_hmma<<<grid, THREADS, SM_TOTAL>>>(x, b1, b2, wn, bn, out);
}

// round 16
// speedup vs baseline: 1.0628x; 1.0628x over previous
#include <cuda_runtime.h>
#include <cuda_fp16.h>
#include <cstdint>

#define DIMC 128
#define HID  512
#define TILE_M 64
#define THREADS 128
#define EPSV 1e-5f

#define ROWB 272
#define ATILE_BYTES (64 * ROWB)        // 17408

// ---- smem: xn + 4 H chunk buffers = 87040 -> 2 CTAs/SM
#define SM_XN 0
#define SM_H  (SM_XN + ATILE_BYTES)
#define SM_TOTAL (SM_H + 4 * ATILE_BYTES)

// ---- fragment-ordered fp16 weight images: [chunk][nw][iter=ks*4+ng][lane]
__device__ __align__(16) uint4 g_w1f[4][2][32][32];
__device__ __align__(16) uint4 g_w2f[4][2][32][32];

// ---------------- PTX helpers ----------------
__device__ __forceinline__ uint32_t smem_u32(const void* p) {
    uint32_t a;
    asm("{ .reg .u64 t; cvta.to.shared.u64 t, %1; cvt.u32.u64 %0, t; }" : "=r"(a) : "l"(p));
    return a;
}

__device__ __forceinline__ void ldsm4(uint32_t r[4], uint32_t addr) {
    asm volatile("ldmatrix.sync.aligned.m8n8.x4.shared.b16 {%0,%1,%2,%3}, [%4];"
                 : "=r"(r[0]), "=r"(r[1]), "=r"(r[2]), "=r"(r[3]) : "r"(addr));
}

__device__ __forceinline__ void mma16816(float c[4], const uint32_t a[4],
                                         uint32_t b0, uint32_t b1) {
    asm volatile(
        "mma.sync.aligned.m16n8k16.row.col.f32.f16.f16.f32 "
        "{%0,%1,%2,%3}, {%4,%5,%6,%7}, {%8,%9}, {%0,%1,%2,%3};"
        : "+f"(c[0]), "+f"(c[1]), "+f"(c[2]), "+f"(c[3])
        : "r"(a[0]), "r"(a[1]), "r"(a[2]), "r"(a[3]), "r"(b0), "r"(b1));
}

__device__ __forceinline__ uint32_t pack_f16x2(float lo, float hi) {
    uint32_t r;
    asm("cvt.rn.f16x2.f32 %0, %1, %2;" : "=r"(r) : "f"(hi), "f"(lo));
    return r;
}

__device__ __forceinline__ uint32_t relu_bias_h2(uint32_t v, uint32_t bias) {
    const __half2 z = __float2half2_rn(0.0f);
    __half2 h = __hadd2(*(__half2*)&v, *(__half2*)&bias);
    h = __hmax2(h, z);
    return *(uint32_t*)&h;
}

__device__ __forceinline__ uint32_t pack2h(__half a, __half b) {
    __half2 t; t.x = a; t.y = b;
    return *(uint32_t*)&t;
}

// ---------------- prep: weights -> fragment-ordered fp16 images ----------
__global__ void prep_weights(const float* __restrict__ w1, const float* __restrict__ w2) {
    const int idx  = blockIdx.x * blockDim.x + threadIdx.x;   // 0..16383
    const int lane = idx & 31;
    const int iter = (idx >> 5) & 31;
    const int nw   = (idx >> 10) & 1;
    const int c    = (idx >> 11) & 3;
    const int mat  = idx >> 13;

    const int ks = iter >> 2, ng = iter & 3;
    const int n0 = nw * 64 + ng * 16 + (lane >> 2);
    const int k0 = ks * 16 + (lane & 3) * 2;

    uint4 v;
    if (mat == 0) {
        #define E1(n, k) __float2half_rn(w1[(size_t)(c * 128 + (n)) * DIMC + (k)])
        v.x = pack2h(E1(n0,     k0),     E1(n0,     k0 + 1));
        v.y = pack2h(E1(n0,     k0 + 8), E1(n0,     k0 + 9));
        v.z = pack2h(E1(n0 + 8, k0),     E1(n0 + 8, k0 + 1));
        v.w = pack2h(E1(n0 + 8, k0 + 8), E1(n0 + 8, k0 + 9));
        #undef E1
        g_w1f[c][nw][iter][lane] = v;
    } else {
        #define E2(n, k) __float2half_rn(w2[(size_t)(n) * HID + c * 128 + (k)])
        v.x = pack2h(E2(n0,     k0),     E2(n0,     k0 + 1));
        v.y = pack2h(E2(n0,     k0 + 8), E2(n0,     k0 + 9));
        v.z = pack2h(E2(n0 + 8, k0),     E2(n0 + 8, k0 + 1));
        v.w = pack2h(E2(n0 + 8, k0 + 8), E2(n0 + 8, k0 + 9));
        #undef E2
        g_w2f[c][nw][iter][lane] = v;
    }
}

#define ZERO_ACC(A) \
    { _Pragma("unroll") for (int i = 0; i < 2; ++i) \
      _Pragma("unroll") for (int j = 0; j < 8; ++j) \
      _Pragma("unroll") for (int k = 0; k < 4; ++k) (A)[i][j][k] = 0.0f; }

// preload B fragments for one ks-step into rbuf
#define PRELOAD_B(rbuf, bp, off) \
    { _Pragma("unroll") for (int _ng = 0; _ng < 4; ++_ng) \
          (rbuf)[_ng] = __ldg((bp) + (off) + _ng * 32); }

// one ks step with prefetch: consume rbuf, refill from bp+nextoff (if PF)
// nextoff in uint4 units; a0/a1 loaded from smem here.
__device__ __forceinline__ void gemm_ks_pf(uint32_t aAddr, int ks,
                                           const uint4* __restrict__ bp,
                                           int nextoff, bool pf,
                                           uint4 rbuf[4], float acc[2][8][4]) {
    uint32_t a0[4], a1[4];
    ldsm4(a0, aAddr + ks * 32);
    ldsm4(a1, aAddr + 16 * ROWB + ks * 32);
    #pragma unroll
    for (int ng = 0; ng < 4; ++ng) {
        const uint4 rb = rbuf[ng];
        if (pf) rbuf[ng] = __ldg(bp + nextoff + ng * 32);
        mma16816(acc[0][2*ng],   a0, rb.x, rb.y);
        mma16816(acc[1][2*ng],   a1, rb.x, rb.y);
        mma16816(acc[0][2*ng+1], a0, rb.z, rb.w);
        mma16816(acc[1][2*ng+1], a1, rb.z, rb.w);
    }
}

// ---------------- main fused kernel ----------------
__global__ void __launch_bounds__(THREADS, 2)
fused_ln_mlp_hmma(const float* __restrict__ x,
                  const float* __restrict__ b1,
                  const float* __restrict__ b2,
                  const float* __restrict__ wn,
                  const float* __restrict__ bn,
                  float* __restrict__ out)
{
    extern __shared__ __align__(16) unsigned char smem[];
    const uint32_t sb = smem_u32(smem);

    const int tid  = threadIdx.x;
    const int lane = tid & 31;
    const int warp = tid >> 5;
    const int mw   = warp & 1;
    const int nw   = warp >> 1;
    const long long m0 = (long long)blockIdx.x * TILE_M;

    // -------- Stage A: LayerNorm -> xn fp16 tile --------
    {
        const float4 wn4 = *(const float4*)(wn + lane * 4);
        const float4 bn4 = *(const float4*)(bn + lane * 4);
        #pragma unroll
        for (int t = 0; t < 16; ++t) {
            const int tok = warp * 16 + t;
            float4 v = *(const float4*)(x + (m0 + tok) * DIMC + lane * 4);
            float s = v.x + v.y + v.z + v.w;
            float q = v.x*v.x + v.y*v.y + v.z*v.z + v.w*v.w;
            #pragma unroll
            for (int o = 16; o > 0; o >>= 1) {
                s += __shfl_xor_sync(0xffffffffu, s, o);
                q += __shfl_xor_sync(0xffffffffu, q, o);
            }
            const float mu  = s * (1.0f / DIMC);
            const float var = q * (1.0f / DIMC) - mu * mu;
            const float r   = rsqrtf(var + EPSV);
            const uint32_t p0 = pack_f16x2((v.x - mu) * r * wn4.x + bn4.x,
                                           (v.y - mu) * r * wn4.y + bn4.y);
            const uint32_t p1 = pack_f16x2((v.z - mu) * r * wn4.z + bn4.z,
                                           (v.w - mu) * r * wn4.w + bn4.w);
            const uint32_t off = (uint32_t)tok * ROWB + lane * 8;
            *(uint2*)(smem + SM_XN + off) = make_uint2(p0, p1);
        }
    }
    __syncthreads();

    // per-thread addressing
    const uint32_t a_row = (uint32_t)(mw * 32 + (lane & 15)) * ROWB + ((lane >> 4) << 4);
    const uint32_t aXn   = sb + SM_XN + a_row;
    const uint32_t h_sts0 = (uint32_t)(mw * 32 + (lane >> 2)) * ROWB
                          + (uint32_t)(nw * 64 + (lane & 3) * 2) * 2;
    const int colb = nw * 64 + (lane & 3) * 2;

    // chunk stride inside a weight image, in uint4 units (nw,lane fixed):
    // g_w1f[c][nw][iter][lane]: c stride = 2*32*32 = 2048, iter stride = 32
    const uint4* __restrict__ w1base = &g_w1f[0][nw][0][lane];
    const uint4* __restrict__ w2base = &g_w2f[0][nw][0][lane];

    // -------- Phase 1: G1 chunks, single acc, hp stores hidden, B prefetch
    float acc[2][8][4];
    uint32_t hp[16][2];
    uint4 rbuf[4];

    // chunk 0 MMA (preload exposed once)
    ZERO_ACC(acc);
    PRELOAD_B(rbuf, w1base, 0);
    #pragma unroll
    for (int ks = 0; ks < 8; ++ks)
        gemm_ks_pf(aXn, ks, w1base, (ks + 1) * 4 * 32, ks < 7, rbuf, acc);

    #pragma unroll
    for (int c = 0; c < 4; ++c) {
        // preload next chunk's first B step NOW (covered by pack epilogue)
        if (c < 3) PRELOAD_B(rbuf, w1base, (c + 1) * 2048);

        // pack chunk c: +b1 (half2), relu -> hp; acc dies here
        {
            const float* b1c = b1 + c * 128;
            #pragma unroll
            for (int mt = 0; mt < 2; ++mt)
                #pragma unroll
                for (int nt = 0; nt < 8; ++nt) {
                    const uint32_t hb = pack_f16x2(__ldg(b1c + colb + nt * 8),
                                                   __ldg(b1c + colb + nt * 8 + 1));
                    hp[mt * 8 + nt][0] =
                        relu_bias_h2(pack_f16x2(acc[mt][nt][0], acc[mt][nt][1]), hb);
                    hp[mt * 8 + nt][1] =
                        relu_bias_h2(pack_f16x2(acc[mt][nt][2], acc[mt][nt][3]), hb);
                }
        }

        const uint32_t hbase = SM_H + (uint32_t)c * ATILE_BYTES + h_sts0;

        if (c < 3) {
            // chunk c+1 MMA loop with interleaved hp(c) stores
            ZERO_ACC(acc);
            const int cb = (c + 1) * 2048;
            #pragma unroll
            for (int ks = 0; ks < 8; ++ks) {
                gemm_ks_pf(aXn, ks, w1base, cb + (ks + 1) * 4 * 32, ks < 7, rbuf, acc);
                #pragma unroll
                for (int f = 2 * ks; f < 2 * ks + 2; ++f) {
                    const int mt = f >> 3, nt = f & 7;
                    const uint32_t o0 = hbase + (uint32_t)mt * (16 * ROWB) + nt * 16;
                    *(uint32_t*)(smem + o0)            = hp[f][0];
                    *(uint32_t*)(smem + o0 + 8 * ROWB) = hp[f][1];
                }
            }
        } else {
            #pragma unroll
            for (int f = 0; f < 16; ++f) {
                const int mt = f >> 3, nt = f & 7;
                const uint32_t o0 = hbase + (uint32_t)mt * (16 * ROWB) + nt * 16;
                *(uint32_t*)(smem + o0)            = hp[f][0];
                *(uint32_t*)(smem + o0 + 8 * ROWB) = hp[f][1];
            }
        }
    }

    __syncthreads();   // all H chunks visible

    // -------- Phase 2: G2 as one flat loop, prefetch chains across chunks -
    float acc2[2][8][4];
    ZERO_ACC(acc2);

    PRELOAD_B(rbuf, w2base, 0);
    #pragma unroll
    for (int f = 0; f < 32; ++f) {
        const int c  = f >> 3;
        const int ks = f & 7;
        const uint32_t hA = sb + SM_H + (uint32_t)c * ATILE_BYTES + a_row;
        const int nf = f + 1;
        const int nextoff = (nf >> 3) * 2048 + (nf & 7) * 4 * 32;
        gemm_ks_pf(hA, ks, w2base, nextoff, f < 31, rbuf, acc2);
    }

    // -------- final epilogue: acc2 + b2 -> out --------
    #pragma unroll
    for (int mt = 0; mt < 2; ++mt) {
        const long long row0 = m0 + mw * 32 + mt * 16 + (lane >> 2);
        #pragma unroll
        for (int nt = 0; nt < 8; ++nt) {
            const int col = nw * 64 + nt * 8 + (lane & 3) * 2;
            const float bb0 = __ldg(b2 + col), bb1 = __ldg(b2 + col + 1);
            float2 u, w;
            u.x = acc2[mt][nt][0] + bb0;  u.y = acc2[mt][nt][1] + bb1;
            w.x = acc2[mt][nt][2] + bb0;  w.y = acc2[mt][nt][3] + bb1;
            *(float2*)(out + row0 * DIMC + col)       = u;
            *(float2*)(out + (row0 + 8) * DIMC + col) = w;
        }
    }
}

extern "C" void kernel_launch(void* const* d_in, const int* in_sizes, int n_in,
                              void* d_out, int out_size) {
    const float* x  = (const float*)d_in[0];
    const float* w1 = (const float*)d_in[1];
    const float* w2 = (const float*)d_in[2];
    const float* b1 = (const float*)d_in[3];
    const float* b2 = (const float*)d_in[4];
    const float* wn = (const float*)d_in[5];
    const float* bn = (const float*)d_in[6];
    float* out = (float*)d_out;

    prep_weights<<<64, 256>>>(w1, w2);

    const int T = in_sizes[0] / DIMC;        // 262144 tokens
    const int grid = T / TILE_M;             // 4096 CTAs

    cudaFuncSetAttribute(fused_ln_mlp_hmma,
                         cudaFuncAttributeMaxDynamicSharedMemorySize, SM_TOTAL);
    fused_ln_mlp_hmma<<<grid, THREADS, SM_TOTAL>>>(x, b1, b2, wn, bn, out);
}